// round 6
// baseline (speedup 1.0000x reference)
#include <cuda_runtime.h>
#include <stdint.h>

#define NBINS   29
#define BB      64
#define CC      4
#define QQ      32
#define DD      4096

#define THREADS 256
#define ITERS   4                 // 1024 int4 positions / 256 threads
#define CSTRIDE (QQ * DD / 4)     // channel stride in float4 units = 32768

#define HIST_WORDS (NBINS * THREADS)   // 29*256 u32 words = 29.7 KB

__device__ __forceinline__ void proc_elem(float x, int m, uint8_t* col) {
    // bit-exact: ((x + 1.00001) / 2 * 28) trunc -> int.
    // (x+c)*0.5 is exact, so ((x+c)*0.5)*28 == (x+c)*14 with identical rounding.
    float t = __fmul_rn(__fadd_rn(x, 1.00001f), 14.0f);
    unsigned bin = (unsigned)__float2int_rz(t);
    bin = min(bin, 28u);                 // memory-safety clamp only
    if (m) col[bin << 10] += (uint8_t)1; // stride 1024 B per bin
}

__global__ __launch_bounds__(THREADS)
void CountHistogram_kernel(const float* __restrict__ simmat,
                           const int* __restrict__ mask,
                           float* __restrict__ out) {
    // Layout: hist8[bin][channel][thread]  (byte = bin*1024 + c*256 + tid).
    // Each thread owns 4 independent u8 RMW chains (one per channel).
    // Lanes 4k..4k+3 share a 32-bit word (different bytes) -> merged, no
    // bank conflicts; 8 words in 8 distinct banks per warp access.
    __shared__ uint32_t histw[HIST_WORDS];
    uint8_t* hist8 = (uint8_t*)histw;

    const int tid = threadIdx.x;
    const int bq  = blockIdx.x;            // 0 .. B*Q-1
    const int b   = bq / QQ;
    const int q   = bq % QQ;

    #pragma unroll
    for (int i = 0; i < NBINS; i++) histw[i * THREADS + tid] = 0u;
    __syncthreads();

    const float4* srow = (const float4*)simmat +
                         (((size_t)b * CC) * QQ + q) * (DD / 4);   // channel 0
    const int4*   mrow = (const int4*)mask +
                         (((size_t)b * QQ + q) * (DD / 4));

    uint8_t* col = hist8 + tid;            // + c*256 selects the channel stream

    #pragma unroll 1
    for (int k = 0; k < ITERS; k++) {
        const int v = tid + k * THREADS;
        int4   m4 = mrow[v];
        float4 s0 = srow[v];
        float4 s1 = srow[v +     CSTRIDE];
        float4 s2 = srow[v + 2 * CSTRIDE];
        float4 s3 = srow[v + 3 * CSTRIDE];

        proc_elem(s0.x, m4.x, col);        proc_elem(s1.x, m4.x, col + 256);
        proc_elem(s2.x, m4.x, col + 512);  proc_elem(s3.x, m4.x, col + 768);
        proc_elem(s0.y, m4.y, col);        proc_elem(s1.y, m4.y, col + 256);
        proc_elem(s2.y, m4.y, col + 512);  proc_elem(s3.y, m4.y, col + 768);
        proc_elem(s0.z, m4.z, col);        proc_elem(s1.z, m4.z, col + 256);
        proc_elem(s2.z, m4.z, col + 512);  proc_elem(s3.z, m4.z, col + 768);
        proc_elem(s0.w, m4.w, col);        proc_elem(s1.w, m4.w, col + 256);
        proc_elem(s2.w, m4.w, col + 512);  proc_elem(s3.w, m4.w, col + 768);
    }
    __syncthreads();

    // Output (c, bin) = sum of 256 contiguous bytes = 64 words via dp4a.
    // Word idx = bin*256 + c*64 + j; rotate j by bin so the 29 active lanes
    // hit distinct banks (bank = j mod 32).
    if (tid < CC * NBINS) {
        const int co  = tid / NBINS;
        const int bin = tid % NBINS;
        const uint32_t* base = histw + bin * (THREADS) + co * 64;
        unsigned s = 0u;
        #pragma unroll 8
        for (int i = 0; i < 64; i++) {
            const int j = (bin + i) & 63;
            s = __dp4a(base[j], 0x01010101u, s);
        }
        out[((((size_t)b * CC + co) * QQ + q) * NBINS) + bin] = (float)s;
    }
}

extern "C" void kernel_launch(void* const* d_in, const int* in_sizes, int n_in,
                              void* d_out, int out_size) {
    const float* simmat = (const float*)d_in[0];
    const int*   mask   = (const int*)d_in[1];
    float*       out    = (float*)d_out;
    (void)in_sizes; (void)n_in; (void)out_size;

    dim3 grid(BB * QQ);     // 2048 blocks, one per (b, q)
    dim3 block(THREADS);
    CountHistogram_kernel<<<grid, block>>>(simmat, mask, out);
}

// round 9
// speedup vs baseline: 1.4316x; 1.4316x over previous
#include <cuda_runtime.h>
#include <stdint.h>

#define NBINS   29
#define BB      64
#define CC      4
#define QQ      32
#define DD      4096

#define THREADS 256
#define TPC     64          // threads per channel group
#define CHUNK   4           // iterations prefetched together
#define NCHUNK  4           // 16 total float4 iterations per thread

#define HIST_WORDS (NBINS * THREADS)   // 29*256 u32 words = 29.7 KB

__device__ __forceinline__ void proc_elem(float x, int m, uint8_t* col) {
    // bit-exact: ((x + 1.00001) / 2 * 28) trunc -> int.
    // (x+c)*0.5 is exact, so ((x+c)*0.5)*28 == (x+c)*14 with identical rounding.
    float t = __fmul_rn(__fadd_rn(x, 1.00001f), 14.0f);
    unsigned bin = (unsigned)__float2int_rz(t);
    bin = min(bin, 28u);                 // memory-safety clamp only
    if (m) col[bin << 10] += (uint8_t)1; // stride 1024 B per bin
}

__global__ __launch_bounds__(THREADS)
void CountHistogram_kernel(const float* __restrict__ simmat,
                           const int* __restrict__ mask,
                           float* __restrict__ out) {
    // R5 layout: 4 u8 streams per thread (one per float4 lane).
    // byte = bin*1024 + 4*tid + s -> word = bin*256 + tid -> bank = tid%32:
    // conflict-free for any bin pattern, 4 independent RMW chains per thread.
    __shared__ uint32_t histw[HIST_WORDS];
    uint8_t* hist8 = (uint8_t*)histw;

    const int tid = threadIdx.x;
    const int bq  = blockIdx.x;            // 0 .. B*Q-1
    const int b   = bq / QQ;
    const int q   = bq % QQ;

    #pragma unroll
    for (int i = 0; i < NBINS; i++) histw[i * THREADS + tid] = 0u;
    __syncthreads();

    const int c      = tid >> 6;           // channel group 0..3
    const int lane64 = tid & 63;

    const float4* srow = (const float4*)(simmat +
                          ((((size_t)b * CC + c) * QQ + q) * (size_t)DD));
    const int4*   mrow = (const int4*)(mask +
                          (((size_t)b * QQ + q) * (size_t)DD));

    uint8_t* col = hist8 + 4 * tid;        // stream s uses col + s

    // Software pipeline: 8 LDG.128 per chunk, batched one chunk ahead.
    float4 sA[CHUNK]; int4 mA[CHUNK];
    #pragma unroll
    for (int j = 0; j < CHUNK; j++) {
        const int v = lane64 + j * TPC;
        sA[j] = srow[v];
        mA[j] = mrow[v];
    }

    #pragma unroll
    for (int chunk = 0; chunk < NCHUNK; chunk++) {
        float4 sB[CHUNK]; int4 mB[CHUNK];
        if (chunk < NCHUNK - 1) {
            #pragma unroll
            for (int j = 0; j < CHUNK; j++) {
                const int v = lane64 + ((chunk + 1) * CHUNK + j) * TPC;
                sB[j] = srow[v];
                mB[j] = mrow[v];
            }
        }
        #pragma unroll
        for (int j = 0; j < CHUNK; j++) {
            proc_elem(sA[j].x, mA[j].x, col + 0);
            proc_elem(sA[j].y, mA[j].y, col + 1);
            proc_elem(sA[j].z, mA[j].z, col + 2);
            proc_elem(sA[j].w, mA[j].w, col + 3);
        }
        #pragma unroll
        for (int j = 0; j < CHUNK; j++) { sA[j] = sB[j]; mA[j] = mB[j]; }
    }
    __syncthreads();

    // Reduce: output (c, bin) sums 256 bytes = 64 u32 words via dp4a.
    // Rotate j by bin so the 29 active lanes hit distinct banks.
    if (tid < CC * NBINS) {
        const int co  = tid / NBINS;
        const int bin = tid % NBINS;
        const uint32_t* base = histw + bin * THREADS + co * TPC;
        unsigned s = 0u;
        #pragma unroll 8
        for (int i = 0; i < TPC; i++) {
            const int j = (bin + i) & (TPC - 1);
            s = __dp4a(base[j], 0x01010101u, s);
        }
        out[((((size_t)b * CC + co) * QQ + q) * NBINS) + bin] = (float)s;
    }
}

extern "C" void kernel_launch(void* const* d_in, const int* in_sizes, int n_in,
                              void* d_out, int out_size) {
    const float* simmat = (const float*)d_in[0];
    const int*   mask   = (const int*)d_in[1];
    float*       out    = (float*)d_out;
    (void)in_sizes; (void)n_in; (void)out_size;

    dim3 grid(BB * QQ);     // 2048 blocks, one per (b, q)
    dim3 block(THREADS);
    CountHistogram_kernel<<<grid, block>>>(simmat, mask, out);
}